// round 2
// baseline (speedup 1.0000x reference)
#include <cuda_runtime.h>
#include <cstdint>

// Problem constants
#define B   16
#define NC  31
#define NO  3
#define NX  256
#define NY  256
#define NLOC 7533          // 3*31*81
#define NGRP 93            // 3*31

// Tiling
#define TILE_H 32
#define TILE_W 128
#define THR    128         // 8 thread-rows x 16 thread-cols
#define TH     4           // output rows per thread
#define TW     8           // output cols per thread
#define SROWS  40          // TILE_H + 8 halo
#define SCOLS  136         // TILE_W + 8 halo
#define SPITCH 136

__device__ float g_w[NLOC];   // relu'd compact weights, (o,c,dy,dx) order
__device__ int   g_off[NGRP]; // per (o,c) column offset cx-8 in [-4,4]

// ---- packed f32x2 helpers (sm_103a FFMA2) ----
__device__ __forceinline__ unsigned long long pk2(float lo, float hi) {
    unsigned long long r;
    asm("mov.b64 %0, {%1, %2};" : "=l"(r) : "f"(lo), "f"(hi));
    return r;
}
__device__ __forceinline__ void fma2(unsigned long long& acc,
                                     unsigned long long a,
                                     unsigned long long b) {
    asm("fma.rn.f32x2 %0, %1, %2, %0;" : "+l"(acc) : "l"(a), "l"(b));
}
__device__ __forceinline__ void unpk2(unsigned long long v, float& lo, float& hi) {
    asm("mov.b64 {%0, %1}, %2;" : "=f"(lo), "=f"(hi) : "l"(v));
}

// ---- prep: relu weights + extract per-group column offsets ----
__global__ void prep_kernel(const float* __restrict__ vk,
                            const int* __restrict__ loc) {
    int t = blockIdx.x * blockDim.x + threadIdx.x;
    if (t < NLOC) g_w[t] = fmaxf(vk[t], 0.0f);
    if (t < NGRP) {
        // first entry of each 81-group is (dy=-4, dx=-4): kx = cx-4
        int loc0 = loc[t * 81];
        g_off[t] = (loc0 % 17) - 4;   // cx - 8
    }
}

// ---- main conv: one block = (b, o, 32x128 tile) ----
__global__ __launch_bounds__(THR)
void conv_kernel(const float* __restrict__ x, float* __restrict__ out) {
    __shared__ float s_in[SROWS * SPITCH];

    const int bz = blockIdx.z;
    const int b  = bz / NO;
    const int o  = bz % NO;
    const int y0 = blockIdx.y * TILE_H;
    const int x0 = blockIdx.x * TILE_W;

    const int tid = threadIdx.x;
    const int twi = tid & 15;        // 0..15
    const int thi = tid >> 4;        // 0..7
    const int h0  = thi * TH;        // tile-local out row base
    const int w0  = twi * TW;        // tile-local out col base

    unsigned long long acc[TH][4];
    #pragma unroll
    for (int i = 0; i < TH; i++)
        #pragma unroll
        for (int j = 0; j < 4; j++) acc[i][j] = 0ULL;

    for (int c = 0; c < NC; c++) {
        const int oc = g_off[o * NC + c];
        const float* __restrict__ xc = x + ((size_t)(b * NC + c)) * (NX * NY);
        const int gx0 = x0 - 4 + oc;

        // stage channel tile into smem, folding oc into the address
        #pragma unroll 4
        for (int i = tid; i < SROWS * SCOLS; i += THR) {
            int row = i / SCOLS;
            int col = i - row * SCOLS;
            int gy = y0 + row - 4;
            int gx = gx0 + col;
            float v = 0.0f;
            if ((unsigned)gy < (unsigned)NX && (unsigned)gx < (unsigned)NY)
                v = __ldg(xc + gy * NY + gx);
            s_in[i] = v;
        }
        __syncthreads();

        const float* __restrict__ wbase = g_w + (o * NC + c) * 81;

        #pragma unroll
        for (int r = 0; r < TH + 8; r++) {       // 12 input rows
            const float4* src =
                (const float4*)&s_in[(h0 + r) * SPITCH + w0];
            float4 a0 = src[0], a1 = src[1], a2 = src[2], a3 = src[3];
            float v[16] = { a0.x, a0.y, a0.z, a0.w,
                            a1.x, a1.y, a1.z, a1.w,
                            a2.x, a2.y, a2.z, a2.w,
                            a3.x, a3.y, a3.z, a3.w };
            unsigned long long p[15];
            #pragma unroll
            for (int k = 0; k < 15; k++) p[k] = pk2(v[k], v[k + 1]);

            #pragma unroll
            for (int hh = 0; hh < TH; hh++) {
                const int dyi = r - hh;          // dy + 4
                if (dyi < 0 || dyi > 8) continue;
                const float* __restrict__ wr = wbase + dyi * 9;
                #pragma unroll
                for (int dx = 0; dx < 9; dx++) {
                    float wv = __ldg(wr + dx);
                    unsigned long long wp = pk2(wv, wv);
                    fma2(acc[hh][0], wp, p[dx + 0]);
                    fma2(acc[hh][1], wp, p[dx + 2]);
                    fma2(acc[hh][2], wp, p[dx + 4]);
                    fma2(acc[hh][3], wp, p[dx + 6]);
                }
            }
        }
        __syncthreads();
    }

    // write 4 rows x 8 cols per thread
    float* __restrict__ op =
        out + (((size_t)(b * NO + o)) * NX + (y0 + h0)) * NY + x0 + w0;
    #pragma unroll
    for (int hh = 0; hh < TH; hh++) {
        float r0, r1, r2, r3, r4, r5, r6, r7;
        unpk2(acc[hh][0], r0, r1);
        unpk2(acc[hh][1], r2, r3);
        unpk2(acc[hh][2], r4, r5);
        unpk2(acc[hh][3], r6, r7);
        float4 lo = make_float4(r0, r1, r2, r3);
        float4 hi = make_float4(r4, r5, r6, r7);
        *(float4*)(op + hh * NY)     = lo;
        *(float4*)(op + hh * NY + 4) = hi;
    }
}

extern "C" void kernel_launch(void* const* d_in, const int* in_sizes, int n_in,
                              void* d_out, int out_size) {
    const float* x   = (const float*)d_in[0];
    const float* vk  = (const float*)d_in[1];
    const int*   loc = (const int*)d_in[2];
    float* out = (float*)d_out;

    prep_kernel<<<30, 256>>>(vk, loc);

    dim3 grid(NY / TILE_W, NX / TILE_H, B * NO);   // (2, 8, 48)
    conv_kernel<<<grid, THR>>>(x, out);
}

// round 5
// speedup vs baseline: 1.0953x; 1.0953x over previous
#include <cuda_runtime.h>
#include <cstdint>

// Problem constants
#define B   16
#define NC  31
#define NO  3
#define NX  256
#define NY  256
#define NLOC 7533          // 3*31*81
#define NGRP 93            // 3*31

// Tiling
#define TILE_H 32
#define TILE_W 128
#define THR    128         // 8 thread-rows x 16 thread-cols
#define TH     4           // output rows per thread
#define HALF   64          // lane split: f32x2 lanes are cols (w, w+64)
#define SROWS  40          // TILE_H + 8 halo
#define SP2    72          // float2 pairs per smem row (68 needed + overlap)

__device__ float2 g_w2[NLOC];  // relu'd weights duplicated into both lanes
__device__ int    g_off[NGRP]; // per (o,c) column offset cx-8 in [-4,4]

__device__ __forceinline__ void fma2(unsigned long long& acc,
                                     unsigned long long a,
                                     unsigned long long b) {
    asm("fma.rn.f32x2 %0, %1, %2, %0;" : "+l"(acc) : "l"(a), "l"(b));
}
__device__ __forceinline__ void unpk2(unsigned long long v, float& lo, float& hi) {
    asm("mov.b64 {%0, %1}, %2;" : "=f"(lo), "=f"(hi) : "l"(v));
}

// ---- prep: relu + duplicate weights, extract per-group column offsets ----
__global__ void prep_kernel(const float* __restrict__ vk,
                            const int* __restrict__ loc) {
    int t = blockIdx.x * blockDim.x + threadIdx.x;
    if (t < NLOC) {
        float w = fmaxf(vk[t], 0.0f);
        g_w2[t] = make_float2(w, w);
    }
    if (t < NGRP) {
        // first entry of each 81-group is (dy=-4, dx=-4): kx = cx-4
        int loc0 = loc[t * 81];
        g_off[t] = (loc0 % 17) - 4;   // cx - 8
    }
}

// ---- main conv: one block = (b, o, 32x128 tile) ----
__global__ __launch_bounds__(THR)
void conv_kernel(const float* __restrict__ x, float* __restrict__ out) {
    __shared__ float2 s2[SROWS * SP2];   // pair i = (in[gx0+i], in[gx0+64+i])
    __shared__ float2 ws[81];            // channel weights, duplicated lanes

    const int bz = blockIdx.z;
    const int b  = bz / NO;
    const int o  = bz % NO;
    const int y0 = blockIdx.y * TILE_H;
    const int x0 = blockIdx.x * TILE_W;

    const int tid = threadIdx.x;
    const int twi = tid & 15;        // 0..15
    const int thi = tid >> 4;        // 0..7
    const int h0  = thi * TH;        // tile-local out row base
    const int w0  = twi * 4;         // pair-index base (even -> 16B aligned)

    unsigned long long acc[TH][4];
    #pragma unroll
    for (int i = 0; i < TH; i++)
        #pragma unroll
        for (int j = 0; j < 4; j++) acc[i][j] = 0ULL;

    for (int c = 0; c < NC; c++) {
        const int oc = g_off[o * NC + c];
        const float* __restrict__ xc = x + ((size_t)(b * NC + c)) * (NX * NY);
        const int gx0 = x0 - 4 + oc;

        // stage weights (duplicated pairs) into smem
        if (tid < 81)
            ws[tid] = __ldg(&g_w2[(o * NC + c) * 81 + tid]);

        // stage channel tile into smem, interleaved-pair layout
        #pragma unroll 4
        for (int i = tid; i < SROWS * SP2; i += THR) {
            int row = i / SP2;
            int p   = i - row * SP2;
            int gy  = y0 + row - 4;
            int gxa = gx0 + p;
            int gxb = gxa + HALF;
            float va = 0.0f, vb = 0.0f;
            if ((unsigned)gy < (unsigned)NX) {
                const float* rowp = xc + gy * NY;
                if ((unsigned)gxa < (unsigned)NY) va = __ldg(rowp + gxa);
                if ((unsigned)gxb < (unsigned)NY) vb = __ldg(rowp + gxb);
            }
            s2[i] = make_float2(va, vb);
        }
        __syncthreads();

        const unsigned long long* __restrict__ wsu =
            (const unsigned long long*)ws;

        #pragma unroll
        for (int r = 0; r < TH + 8; r++) {       // 12 input rows
            const ulonglong2* __restrict__ src =
                (const ulonglong2*)&s2[(h0 + r) * SP2 + w0];
            unsigned long long q[12];
            #pragma unroll
            for (int k = 0; k < 6; k++) {
                ulonglong2 u = src[k];
                q[2 * k]     = u.x;
                q[2 * k + 1] = u.y;
            }

            #pragma unroll
            for (int hh = 0; hh < TH; hh++) {
                const int dyi = r - hh;          // dy + 4
                if (dyi < 0 || dyi > 8) continue;
                const unsigned long long* __restrict__ wr = wsu + dyi * 9;
                #pragma unroll
                for (int dx = 0; dx < 9; dx++) {
                    unsigned long long wp = wr[dx];
                    fma2(acc[hh][0], wp, q[dx + 0]);
                    fma2(acc[hh][1], wp, q[dx + 1]);
                    fma2(acc[hh][2], wp, q[dx + 2]);
                    fma2(acc[hh][3], wp, q[dx + 3]);
                }
            }
        }
        __syncthreads();
    }

    // write: lane0 -> cols x0+w0.., lane1 -> cols x0+64+w0..
    float* __restrict__ op =
        out + (((size_t)(b * NO + o)) * NX + (y0 + h0)) * NY + x0 + w0;
    #pragma unroll
    for (int hh = 0; hh < TH; hh++) {
        float a0, b0, a1, b1, a2, b2, a3, b3;
        unpk2(acc[hh][0], a0, b0);
        unpk2(acc[hh][1], a1, b1);
        unpk2(acc[hh][2], a2, b2);
        unpk2(acc[hh][3], a3, b3);
        *(float4*)(op + hh * NY)        = make_float4(a0, a1, a2, a3);
        *(float4*)(op + hh * NY + HALF) = make_float4(b0, b1, b2, b3);
    }
}

extern "C" void kernel_launch(void* const* d_in, const int* in_sizes, int n_in,
                              void* d_out, int out_size) {
    const float* x   = (const float*)d_in[0];
    const float* vk  = (const float*)d_in[1];
    const int*   loc = (const int*)d_in[2];
    float* out = (float*)d_out;

    prep_kernel<<<30, 256>>>(vk, loc);

    dim3 grid(NY / TILE_W, NX / TILE_H, B * NO);   // (2, 8, 48)
    conv_kernel<<<grid, THR>>>(x, out);
}